// round 14
// baseline (speedup 1.0000x reference)
#include <cuda_runtime.h>
#include <cuda_bf16.h>
#include <cstdint>

// out[n] = 0.1*Ax[n] - 0.1*deg[n]*x[n] + 0.9*(S[n] - cnt[n]*x[n]^2)
//
// Edge phase is at the LSU lane-op floor (57M lane ops: hyper edge = 2
// gathers + 3 REDs, adj edge = 1 gather + 1 RED); kernel kept identical to
// the best-measured config. This round only optimizes the epilogue:
// memset node (replaces decode re-zero) + scalar high-occupancy fp32 decode.
//
// Per-node 64-bit packed accumulator, one RED.E.ADD.U64 per edge slot:
//   bits [ 0:40) fixed-point sum of (0.1*x[src]) and (0.9*p), scale 2^30
//   bits [40:52) hyper slot count
//   bits [52:64) adjacency degree

#define MAX_N    524288
#define FX_SCALE 1073741824.0f   // 2^30

__device__ unsigned long long g_acc[MAX_N];

__device__ __forceinline__ unsigned long long pack_hyper(float v) {
    return (1ULL << 40) | (unsigned long long)__float2uint_rn(v * FX_SCALE);
}
__device__ __forceinline__ unsigned long long pack_adj(float v) {
    return (1ULL << 52) | (unsigned long long)__float2uint_rn(v * FX_SCALE);
}

__global__ void edge_kernel(const float* __restrict__ x,
                            const int*   __restrict__ he,   // [nH*3]
                            int nH,
                            const int*   __restrict__ adj,  // [nA*2]
                            int nA,
                            int hyperBlocks)
{
    if ((int)blockIdx.x < hyperBlocks) {
        // ---- hyper edges: 4 edges (12 ints) per thread via 3x streaming int4 ----
        const int g = blockIdx.x * blockDim.x + threadIdx.x;
        const int nGroups = nH >> 2;

        if (g < nGroups) {
            const int4* he4 = (const int4*)he;
            int4 a = __ldcs(he4 + 3 * g + 0);
            int4 b = __ldcs(he4 + 3 * g + 1);
            int4 c = __ldcs(he4 + 3 * g + 2);
            int idx[12] = { a.x, a.y, a.z, a.w,
                            b.x, b.y, b.z, b.w,
                            c.x, c.y, c.z, c.w };
            float xv[8];
            #pragma unroll
            for (int e = 0; e < 4; e++) {
                xv[2 * e + 0] = __ldg(x + idx[3 * e + 1]);
                xv[2 * e + 1] = __ldg(x + idx[3 * e + 2]);
            }
            #pragma unroll
            for (int e = 0; e < 4; e++) {
                float p = 0.9f * xv[2 * e + 0] * xv[2 * e + 1];
                unsigned long long payload = pack_hyper(p);
                atomicAdd(&g_acc[idx[3 * e + 0]], payload);
                atomicAdd(&g_acc[idx[3 * e + 1]], payload);
                atomicAdd(&g_acc[idx[3 * e + 2]], payload);
            }
        }
        // scalar tail (nH % 4)
        int tailStart = nGroups << 2;
        int t = tailStart + g;
        if (t < nH && g < (nH - tailStart)) {
            int i0 = he[3 * t + 0];
            int i1 = he[3 * t + 1];
            int i2 = he[3 * t + 2];
            float p = 0.9f * __ldg(x + i1) * __ldg(x + i2);
            unsigned long long payload = pack_hyper(p);
            atomicAdd(&g_acc[i0], payload);
            atomicAdd(&g_acc[i1], payload);
            atomicAdd(&g_acc[i2], payload);
        }
    } else {
        // ---- adjacency edges: 4 edges per thread via 2x streaming int4 ----
        const int g = ((int)blockIdx.x - hyperBlocks) * blockDim.x + threadIdx.x;
        const int nGroups = nA >> 2;

        if (g < nGroups) {
            const int4* adj4 = (const int4*)adj;
            int4 e0 = __ldcs(adj4 + 2 * g + 0);  // (s0,d0,s1,d1)
            int4 e1 = __ldcs(adj4 + 2 * g + 1);  // (s2,d2,s3,d3)
            float s0 = __ldg(x + e0.x);
            float s1 = __ldg(x + e0.z);
            float s2 = __ldg(x + e1.x);
            float s3 = __ldg(x + e1.z);
            atomicAdd(&g_acc[e0.y], pack_adj(0.1f * s0));
            atomicAdd(&g_acc[e0.w], pack_adj(0.1f * s1));
            atomicAdd(&g_acc[e1.y], pack_adj(0.1f * s2));
            atomicAdd(&g_acc[e1.w], pack_adj(0.1f * s3));
        }
        // scalar tail (nA % 4)
        int tailStart = nGroups << 2;
        int t = tailStart + g;
        if (t < nA && g < (nA - tailStart)) {
            int s = adj[2 * t + 0];
            int d = adj[2 * t + 1];
            atomicAdd(&g_acc[d], pack_adj(0.1f * __ldg(x + s)));
        }
    }
}

__global__ void decode_kernel(const float* __restrict__ x,
                              float*       __restrict__ out,
                              int N)
{
    int n = blockIdx.x * blockDim.x + threadIdx.x;
    if (n >= N) return;
    unsigned long long a = __ldcs(&g_acc[n]);
    // 40-bit fixed sum -> float directly (max ~2^37; f32 rel err ample)
    float sum = (float)(a & ((1ULL << 40) - 1)) * (1.0f / FX_SCALE);
    int cntH = (int)((a >> 40) & 0xFFF);
    int degA = (int)((a >> 52) & 0xFFF);
    float xv = __ldg(x + n);
    float r = sum - 0.1f * (float)degA * xv - 0.9f * (float)cntH * xv * xv;
    __stcs(out + n, r);
}

extern "C" void kernel_launch(void* const* d_in, const int* in_sizes, int n_in,
                              void* d_out, int out_size)
{
    const float* x   = (const float*)d_in[0];
    const int*   he  = (const int*)d_in[2];
    const int*   adj = (const int*)d_in[3];
    float*       out = (float*)d_out;

    const int nH = in_sizes[2] / 3;
    const int nA = in_sizes[3] / 2;
    const int N  = out_size;

    // zero packed accumulators (graph-capturable memset node; cheaper than
    // re-zero stores on the decode critical path)
    void* accPtr = nullptr;
    cudaGetSymbolAddress(&accPtr, g_acc);
    cudaMemsetAsync(accPtr, 0, (size_t)N * sizeof(unsigned long long), 0);

    const int threads = 256;

    int hyperBlocks = ((nH >> 2) + threads - 1) / threads;
    if (hyperBlocks < 1) hyperBlocks = 1;
    int adjBlocks = ((nA >> 2) + threads - 1) / threads;
    if (adjBlocks < 1) adjBlocks = 1;

    edge_kernel<<<hyperBlocks + adjBlocks, threads>>>(x, he, nH, adj, nA,
                                                      hyperBlocks);

    int decBlocks = (N + threads - 1) / threads;
    decode_kernel<<<decBlocks, threads>>>(x, out, N);
}

// round 15
// speedup vs baseline: 1.0007x; 1.0007x over previous
#include <cuda_runtime.h>
#include <cuda_bf16.h>
#include <cstdint>

// out[n] = 0.1*Ax[n] - 0.1*deg[n]*x[n] + 0.9*(S[n] - cnt[n]*x[n]^2)
//
// Edge phase sits at the L1tex wavefront floor (57M divergent lane-ops:
// hyper edge = 2 gathers + 3 REDs, adj edge = 1 gather + 1 RED). This round
// shrinks the non-floor time: 128-thread blocks (smaller T_CTA -> smaller
// last-wave straggle under the MLP_p1 spread model) and PDL on decode
// (overlaps decode launch/prologue with the edge kernel's drain).
//
// Per-node 64-bit packed accumulator, one RED.E.ADD.U64 per edge slot:
//   bits [ 0:40) fixed-point sum of (0.1*x[src]) and (0.9*p), scale 2^30
//   bits [40:52) hyper slot count
//   bits [52:64) adjacency degree

#define MAX_N    524288
#define FX_SCALE 1073741824.0f   // 2^30
#define ETPB     128

__device__ unsigned long long g_acc[MAX_N];

__device__ __forceinline__ unsigned long long pack_hyper(float v) {
    return (1ULL << 40) | (unsigned long long)__float2uint_rn(v * FX_SCALE);
}
__device__ __forceinline__ unsigned long long pack_adj(float v) {
    return (1ULL << 52) | (unsigned long long)__float2uint_rn(v * FX_SCALE);
}

__global__ void edge_kernel(const float* __restrict__ x,
                            const int*   __restrict__ he,   // [nH*3]
                            int nH,
                            const int*   __restrict__ adj,  // [nA*2]
                            int nA,
                            int hyperBlocks)
{
    if ((int)blockIdx.x < hyperBlocks) {
        // ---- hyper edges: 4 edges (12 ints) per thread via 3x streaming int4 ----
        const int g = blockIdx.x * ETPB + threadIdx.x;
        const int nGroups = nH >> 2;

        if (g < nGroups) {
            const int4* he4 = (const int4*)he;
            int4 a = __ldcs(he4 + 3 * g + 0);
            int4 b = __ldcs(he4 + 3 * g + 1);
            int4 c = __ldcs(he4 + 3 * g + 2);
            int idx[12] = { a.x, a.y, a.z, a.w,
                            b.x, b.y, b.z, b.w,
                            c.x, c.y, c.z, c.w };
            float xv[8];
            #pragma unroll
            for (int e = 0; e < 4; e++) {
                xv[2 * e + 0] = __ldg(x + idx[3 * e + 1]);
                xv[2 * e + 1] = __ldg(x + idx[3 * e + 2]);
            }
            #pragma unroll
            for (int e = 0; e < 4; e++) {
                float p = 0.9f * xv[2 * e + 0] * xv[2 * e + 1];
                unsigned long long payload = pack_hyper(p);
                atomicAdd(&g_acc[idx[3 * e + 0]], payload);
                atomicAdd(&g_acc[idx[3 * e + 1]], payload);
                atomicAdd(&g_acc[idx[3 * e + 2]], payload);
            }
        }
        // scalar tail (nH % 4)
        int tailStart = nGroups << 2;
        int t = tailStart + g;
        if (t < nH && g < (nH - tailStart)) {
            int i0 = he[3 * t + 0];
            int i1 = he[3 * t + 1];
            int i2 = he[3 * t + 2];
            float p = 0.9f * __ldg(x + i1) * __ldg(x + i2);
            unsigned long long payload = pack_hyper(p);
            atomicAdd(&g_acc[i0], payload);
            atomicAdd(&g_acc[i1], payload);
            atomicAdd(&g_acc[i2], payload);
        }
    } else {
        // ---- adjacency edges: 4 edges per thread via 2x streaming int4 ----
        const int g = ((int)blockIdx.x - hyperBlocks) * ETPB + threadIdx.x;
        const int nGroups = nA >> 2;

        if (g < nGroups) {
            const int4* adj4 = (const int4*)adj;
            int4 e0 = __ldcs(adj4 + 2 * g + 0);  // (s0,d0,s1,d1)
            int4 e1 = __ldcs(adj4 + 2 * g + 1);  // (s2,d2,s3,d3)
            float s0 = __ldg(x + e0.x);
            float s1 = __ldg(x + e0.z);
            float s2 = __ldg(x + e1.x);
            float s3 = __ldg(x + e1.z);
            atomicAdd(&g_acc[e0.y], pack_adj(0.1f * s0));
            atomicAdd(&g_acc[e0.w], pack_adj(0.1f * s1));
            atomicAdd(&g_acc[e1.y], pack_adj(0.1f * s2));
            atomicAdd(&g_acc[e1.w], pack_adj(0.1f * s3));
        }
        // scalar tail (nA % 4)
        int tailStart = nGroups << 2;
        int t = tailStart + g;
        if (t < nA && g < (nA - tailStart)) {
            int s = adj[2 * t + 0];
            int d = adj[2 * t + 1];
            atomicAdd(&g_acc[d], pack_adj(0.1f * __ldg(x + s)));
        }
    }
}

__global__ void decode_kernel(const float* __restrict__ x,
                              float*       __restrict__ out,
                              int N)
{
    // PDL: wait for the edge kernel's full completion (implicit trigger at
    // primary exit includes the memory flush) before reading g_acc.
    cudaGridDependencySynchronize();

    int n = blockIdx.x * blockDim.x + threadIdx.x;
    if (n >= N) return;
    unsigned long long a = __ldcs(&g_acc[n]);
    float sum = (float)(a & ((1ULL << 40) - 1)) * (1.0f / FX_SCALE);
    int cntH = (int)((a >> 40) & 0xFFF);
    int degA = (int)((a >> 52) & 0xFFF);
    float xv = __ldg(x + n);
    float r = sum - 0.1f * (float)degA * xv - 0.9f * (float)cntH * xv * xv;
    __stcs(out + n, r);
}

extern "C" void kernel_launch(void* const* d_in, const int* in_sizes, int n_in,
                              void* d_out, int out_size)
{
    const float* x   = (const float*)d_in[0];
    const int*   he  = (const int*)d_in[2];
    const int*   adj = (const int*)d_in[3];
    float*       out = (float*)d_out;

    const int nH = in_sizes[2] / 3;
    const int nA = in_sizes[3] / 2;
    const int N  = out_size;

    // zero packed accumulators (graph-capturable memset node)
    void* accPtr = nullptr;
    cudaGetSymbolAddress(&accPtr, g_acc);
    cudaMemsetAsync(accPtr, 0, (size_t)N * sizeof(unsigned long long), 0);

    int hyperBlocks = ((nH >> 2) + ETPB - 1) / ETPB;
    if (hyperBlocks < 1) hyperBlocks = 1;
    int adjBlocks = ((nA >> 2) + ETPB - 1) / ETPB;
    if (adjBlocks < 1) adjBlocks = 1;

    edge_kernel<<<hyperBlocks + adjBlocks, ETPB>>>(x, he, nH, adj, nA,
                                                   hyperBlocks);

    // decode with programmatic dependent launch: its prologue overlaps the
    // edge kernel's drain; cudaGridDependencySynchronize() in-kernel ensures
    // correctness.
    const int dThreads = 256;
    int decBlocks = (N + dThreads - 1) / dThreads;

    cudaLaunchConfig_t cfg = {};
    cfg.gridDim  = dim3((unsigned)decBlocks, 1, 1);
    cfg.blockDim = dim3(dThreads, 1, 1);
    cfg.dynamicSmemBytes = 0;
    cfg.stream = 0;
    cudaLaunchAttribute attrs[1];
    attrs[0].id = cudaLaunchAttributeProgrammaticStreamSerialization;
    attrs[0].val.programmaticStreamSerializationAllowed = 1;
    cfg.attrs = attrs;
    cfg.numAttrs = 1;
    cudaLaunchKernelEx(&cfg, decode_kernel, x, out, N);
}

// round 17
// speedup vs baseline: 1.0066x; 1.0058x over previous
#include <cuda_runtime.h>
#include <cuda_bf16.h>
#include <cstdint>

// out[n] = 0.1*Ax[n] - 0.1*deg[n]*x[n] + 0.9*(S[n] - cnt[n]*x[n]^2)
//
// Edge phase sits at the L1tex/LSU lane-op floor (57M random lane-ops:
// hyper edge = 2 gathers + 3 REDs, adj edge = 1 gather + 1 RED). This round
// hides the accumulator-zeroing pass under the edge kernel's prologue via a
// PDL chain: zero_kernel -> (PDL) edge_kernel -> (PDL) decode_kernel.
// edge_kernel issues its streaming edge loads and x gathers BEFORE
// cudaGridDependencySynchronize(), and only then begins atomics on g_acc.
//
// Per-node 64-bit packed accumulator, one RED.E.ADD.U64 per edge slot:
//   bits [ 0:40) fixed-point sum of (0.1*x[src]) and (0.9*p), scale 2^30
//   bits [40:52) hyper slot count
//   bits [52:64) adjacency degree

#define MAX_N    524288
#define FX_SCALE 1073741824.0f   // 2^30
#define ETPB     128

__device__ unsigned long long g_acc[MAX_N];

__device__ __forceinline__ unsigned long long pack_hyper(float v) {
    return (1ULL << 40) | (unsigned long long)__float2uint_rn(v * FX_SCALE);
}
__device__ __forceinline__ unsigned long long pack_adj(float v) {
    return (1ULL << 52) | (unsigned long long)__float2uint_rn(v * FX_SCALE);
}

__global__ void zero_kernel(int N)
{
    // 4 u64 per thread via 2x ulonglong2 streaming stores
    int t = blockIdx.x * blockDim.x + threadIdx.x;
    int base = t * 4;
    ulonglong2 z; z.x = 0ULL; z.y = 0ULL;
    if (base + 3 < N) {
        __stcs((ulonglong2*)(g_acc + base),     z);
        __stcs((ulonglong2*)(g_acc + base + 2), z);
    } else {
        for (int i = base; i < N; i++) g_acc[i] = 0ULL;
    }
}

__global__ void edge_kernel(const float* __restrict__ x,
                            const int*   __restrict__ he,   // [nH*3]
                            int nH,
                            const int*   __restrict__ adj,  // [nA*2]
                            int nA,
                            int hyperBlocks)
{
    if ((int)blockIdx.x < hyperBlocks) {
        // ---- hyper edges: 4 edges (12 ints) per thread via 3x streaming int4 ----
        const int g = blockIdx.x * ETPB + threadIdx.x;
        const int nGroups = nH >> 2;

        if (g < nGroups) {
            const int4* he4 = (const int4*)he;
            int4 a = __ldcs(he4 + 3 * g + 0);
            int4 b = __ldcs(he4 + 3 * g + 1);
            int4 c = __ldcs(he4 + 3 * g + 2);
            int idx[12] = { a.x, a.y, a.z, a.w,
                            b.x, b.y, b.z, b.w,
                            c.x, c.y, c.z, c.w };
            float xv[8];
            #pragma unroll
            for (int e = 0; e < 4; e++) {
                xv[2 * e + 0] = __ldg(x + idx[3 * e + 1]);
                xv[2 * e + 1] = __ldg(x + idx[3 * e + 2]);
            }
            // overlap window ends here: wait for zero_kernel before atomics
            cudaGridDependencySynchronize();
            #pragma unroll
            for (int e = 0; e < 4; e++) {
                float p = 0.9f * xv[2 * e + 0] * xv[2 * e + 1];
                unsigned long long payload = pack_hyper(p);
                atomicAdd(&g_acc[idx[3 * e + 0]], payload);
                atomicAdd(&g_acc[idx[3 * e + 1]], payload);
                atomicAdd(&g_acc[idx[3 * e + 2]], payload);
            }
        } else {
            cudaGridDependencySynchronize();
        }
        // scalar tail (nH % 4)
        int tailStart = nGroups << 2;
        int t = tailStart + g;
        if (t < nH && g < (nH - tailStart)) {
            int i0 = he[3 * t + 0];
            int i1 = he[3 * t + 1];
            int i2 = he[3 * t + 2];
            float p = 0.9f * __ldg(x + i1) * __ldg(x + i2);
            unsigned long long payload = pack_hyper(p);
            atomicAdd(&g_acc[i0], payload);
            atomicAdd(&g_acc[i1], payload);
            atomicAdd(&g_acc[i2], payload);
        }
    } else {
        // ---- adjacency edges: 4 edges per thread via 2x streaming int4 ----
        const int g = ((int)blockIdx.x - hyperBlocks) * ETPB + threadIdx.x;
        const int nGroups = nA >> 2;

        if (g < nGroups) {
            const int4* adj4 = (const int4*)adj;
            int4 e0 = __ldcs(adj4 + 2 * g + 0);  // (s0,d0,s1,d1)
            int4 e1 = __ldcs(adj4 + 2 * g + 1);  // (s2,d2,s3,d3)
            float s0 = __ldg(x + e0.x);
            float s1 = __ldg(x + e0.z);
            float s2 = __ldg(x + e1.x);
            float s3 = __ldg(x + e1.z);
            cudaGridDependencySynchronize();
            atomicAdd(&g_acc[e0.y], pack_adj(0.1f * s0));
            atomicAdd(&g_acc[e0.w], pack_adj(0.1f * s1));
            atomicAdd(&g_acc[e1.y], pack_adj(0.1f * s2));
            atomicAdd(&g_acc[e1.w], pack_adj(0.1f * s3));
        } else {
            cudaGridDependencySynchronize();
        }
        // scalar tail (nA % 4)
        int tailStart = nGroups << 2;
        int t = tailStart + g;
        if (t < nA && g < (nA - tailStart)) {
            int s = adj[2 * t + 0];
            int d = adj[2 * t + 1];
            atomicAdd(&g_acc[d], pack_adj(0.1f * __ldg(x + s)));
        }
    }
}

__global__ void decode_kernel(const float* __restrict__ x,
                              float*       __restrict__ out,
                              int N)
{
    // wait for edge_kernel's full completion (implicit trigger incl. flush)
    cudaGridDependencySynchronize();

    int n = blockIdx.x * blockDim.x + threadIdx.x;
    if (n >= N) return;
    unsigned long long a = __ldcs(&g_acc[n]);
    float sum = (float)(a & ((1ULL << 40) - 1)) * (1.0f / FX_SCALE);
    int cntH = (int)((a >> 40) & 0xFFF);
    int degA = (int)((a >> 52) & 0xFFF);
    float xv = __ldg(x + n);
    float r = sum - 0.1f * (float)degA * xv - 0.9f * (float)cntH * xv * xv;
    __stcs(out + n, r);
}

extern "C" void kernel_launch(void* const* d_in, const int* in_sizes, int n_in,
                              void* d_out, int out_size)
{
    const float* x   = (const float*)d_in[0];
    const int*   he  = (const int*)d_in[2];
    const int*   adj = (const int*)d_in[3];
    float*       out = (float*)d_out;

    const int nH = in_sizes[2] / 3;
    const int nA = in_sizes[3] / 2;
    const int N  = out_size;

    // ---- zero_kernel (replaces memset node; hidden under edge prologue) ----
    {
        const int zThreads = 256;
        int zBlocks = ((N + 3) / 4 + zThreads - 1) / zThreads;
        zero_kernel<<<zBlocks, zThreads>>>(N);
    }

    // ---- edge_kernel with PDL after zero_kernel ----
    {
        int hyperBlocks = ((nH >> 2) + ETPB - 1) / ETPB;
        if (hyperBlocks < 1) hyperBlocks = 1;
        int adjBlocks = ((nA >> 2) + ETPB - 1) / ETPB;
        if (adjBlocks < 1) adjBlocks = 1;

        cudaLaunchConfig_t cfg = {};
        cfg.gridDim  = dim3((unsigned)(hyperBlocks + adjBlocks), 1, 1);
        cfg.blockDim = dim3(ETPB, 1, 1);
        cfg.dynamicSmemBytes = 0;
        cfg.stream = 0;
        cudaLaunchAttribute attrs[1];
        attrs[0].id = cudaLaunchAttributeProgrammaticStreamSerialization;
        attrs[0].val.programmaticStreamSerializationAllowed = 1;
        cfg.attrs = attrs;
        cfg.numAttrs = 1;
        cudaLaunchKernelEx(&cfg, edge_kernel, x, he, nH, adj, nA, hyperBlocks);
    }

    // ---- decode_kernel with PDL after edge_kernel ----
    {
        const int dThreads = 256;
        int decBlocks = (N + dThreads - 1) / dThreads;

        cudaLaunchConfig_t cfg = {};
        cfg.gridDim  = dim3((unsigned)decBlocks, 1, 1);
        cfg.blockDim = dim3(dThreads, 1, 1);
        cfg.dynamicSmemBytes = 0;
        cfg.stream = 0;
        cudaLaunchAttribute attrs[1];
        attrs[0].id = cudaLaunchAttributeProgrammaticStreamSerialization;
        attrs[0].val.programmaticStreamSerializationAllowed = 1;
        cfg.attrs = attrs;
        cfg.numAttrs = 1;
        cudaLaunchKernelEx(&cfg, decode_kernel, x, out, N);
    }
}